// round 15
// baseline (speedup 1.0000x reference)
#include <cuda_runtime.h>

#define NN 4096
#define BB 8
#define CHUNK 128             // senders per block
#define NGROUP (NN / CHUNK)   // 32 sender groups
#define TPB 128               // receivers per block

// strength(v) = (e^v - e^-1)/(e - e^-1) = C1*e^v - C2
#define C1f 0.4254590641196608f
#define C2f 0.1565176423029702f
#define L2E 1.4426950408889634f

// Scratch: [NGROUP][B][N] = 4 MB
__device__ float g_partial[NGROUP * BB * NN];

__device__ __forceinline__ float ex2a(float x) {
    float r; asm("ex2.approx.f32 %0, %1;" : "=f"(r) : "f"(x)); return r;
}
__device__ __forceinline__ float rsqa(float x) {
    float r; asm("rsqrt.approx.f32 %0, %1;" : "=f"(r) : "f"(x)); return r;
}

// Per-sender record (64 B):
//   a = (px, py, pz, |p|^2)
//   b = (ox*L2E, oy*L2E, oz*L2E, -(p.o)*L2E)
//   x0 = x[0..3][i],  x1 = x[4..7][i]
struct SRec { float4 a, b, x0, x1; };

__global__ __launch_bounds__(TPB, 8) void pair_kernel(
    const float* __restrict__ x,
    const float* __restrict__ position,
    const float* __restrict__ indir,
    const float* __restrict__ outdir)
{
    __shared__ SRec sh[CHUNK];   // 8 KB

    const int tid = threadIdx.x;
    const int j   = blockIdx.x * TPB + tid;   // receiver
    const int i0  = blockIdx.y * CHUNK;       // sender base

    // Fill: one sender per thread (CHUNK == TPB)
    {
        const int i = i0 + tid;
        const float px = position[i * 3 + 0];
        const float py = position[i * 3 + 1];
        const float pz = position[i * 3 + 2];
        const float ox = outdir[i * 3 + 0] * L2E;
        const float oy = outdir[i * 3 + 1] * L2E;
        const float oz = outdir[i * 3 + 2] * L2E;
        const float q  = fmaf(px, px, fmaf(py, py, pz * pz));
        const float c  = fmaf(px, ox, fmaf(py, oy, pz * oz)); // (p.o)*L2E
        sh[tid].a  = make_float4(px, py, pz, q);
        sh[tid].b  = make_float4(ox, oy, oz, -c);
        sh[tid].x0 = make_float4(x[0 * NN + i], x[1 * NN + i],
                                 x[2 * NN + i], x[3 * NN + i]);
        sh[tid].x1 = make_float4(x[4 * NN + i], x[5 * NN + i],
                                 x[6 * NN + i], x[7 * NN + i]);
    }

    // Receiver invariants
    const float pjx = position[j * 3 + 0];
    const float pjy = position[j * 3 + 1];
    const float pjz = position[j * 3 + 2];
    const float qj  = fmaf(pjx, pjx, fmaf(pjy, pjy, pjz * pjz));
    const float m2x = -2.f * pjx;
    const float m2y = -2.f * pjy;
    const float m2z = -2.f * pjz;
    const float ijx = indir[j * 3 + 0] * L2E;
    const float ijy = indir[j * 3 + 1] * L2E;
    const float ijz = indir[j * 3 + 2] * L2E;
    const float nix = -ijx, niy = -ijy, niz = -ijz;
    const float ej  = fmaf(pjx, ijx, fmaf(pjy, ijy, pjz * ijz)); // (pj.ij)*L2E

    __syncthreads();

    float a0 = 0.f, a1 = 0.f, a2 = 0.f, a3 = 0.f;
    float a4 = 0.f, a5 = 0.f, a6 = 0.f, a7 = 0.f;

#pragma unroll 4
    for (int s = 0; s < CHUNK; s++) {
        const float4 A  = sh[s].a;
        const float4 Bv = sh[s].b;

        // n2 = |pj - pi|^2 = qi + qj - 2*pi.pj
        const float n2 = fmaf(A.x, m2x, fmaf(A.y, m2y, fmaf(A.z, m2z, A.w + qj)));
        const float rn = rsqa(fmaxf(n2, 1e-5f));

        // da = (pj.oi - pi.oi)*L2E ; db = (pj.ij - pi.ij)*L2E
        const float da = fmaf(Bv.x, pjx, fmaf(Bv.y, pjy, fmaf(Bv.z, pjz, Bv.w)));
        const float db = fmaf(A.x, nix, fmaf(A.y, niy, fmaf(A.z, niz, ej)));

        const float ea = ex2a(da * rn);
        const float eb = ex2a(db * rn);
        const float sa = fmaf(C1f, ea, -C2f);
        const float sb = fmaf(C1f, eb, -C2f);
        const float g  = sa * sb;

        const float4 X0 = sh[s].x0;
        const float4 X1 = sh[s].x1;
        a0 = fmaf(g, X0.x, a0);
        a1 = fmaf(g, X0.y, a1);
        a2 = fmaf(g, X0.z, a2);
        a3 = fmaf(g, X0.w, a3);
        a4 = fmaf(g, X1.x, a4);
        a5 = fmaf(g, X1.y, a5);
        a6 = fmaf(g, X1.z, a6);
        a7 = fmaf(g, X1.w, a7);
    }

    float* outp = g_partial + (size_t)(blockIdx.y * BB) * NN + j;
    outp[0 * NN] = a0;
    outp[1 * NN] = a1;
    outp[2 * NN] = a2;
    outp[3 * NN] = a3;
    outp[4 * NN] = a4;
    outp[5 * NN] = a5;
    outp[6 * NN] = a6;
    outp[7 * NN] = a7;
}

// Reduce: each warp covers 8 consecutive outputs; lane = sub*8 + joff.
// Each lane sums 8 of the 32 partials, coalesced in j; 2-step shfl combine.
__global__ __launch_bounds__(256) void reduce_kernel(
    const float* __restrict__ power,
    const float* __restrict__ bias,
    float* __restrict__ out)
{
    const int t    = blockIdx.x * 256 + threadIdx.x;
    const int warp = t >> 5;
    const int lane = threadIdx.x & 31;
    const int sub  = lane >> 3;              // 0..3 → 8-group quarter
    const int o    = warp * 8 + (lane & 7);  // output index (b,j)
    const int b    = o >> 12;
    const int j    = o & (NN - 1);

    const float* base = g_partial + (size_t)b * NN + j;
    float s = 0.f;
#pragma unroll
    for (int k = 0; k < 8; k++) {
        const int c = sub * 8 + k;
        s += base[(size_t)c * BB * NN];
    }
    s += __shfl_down_sync(0xFFFFFFFFu, s, 8);
    s += __shfl_down_sync(0xFFFFFFFFu, s, 16);

    if (lane < 8) {
        const float z = fmaf(s, power[j], -bias[j]);
        out[o] = (z > 0.f) ? z : expm1f(z);
    }
}

extern "C" void kernel_launch(void* const* d_in, const int* in_sizes, int n_in,
                              void* d_out, int out_size)
{
    const float* x        = (const float*)d_in[0];
    const float* position = (const float*)d_in[1];
    const float* indir    = (const float*)d_in[2];
    const float* outdir   = (const float*)d_in[3];
    const float* power    = (const float*)d_in[4];
    const float* bias     = (const float*)d_in[5];
    float* out = (float*)d_out;

    dim3 grid(NN / TPB, NGROUP);           // 32 x 32 = 1024 blocks, single wave
    pair_kernel<<<grid, TPB>>>(x, position, indir, outdir);
    // 32768 outputs * 4 sub-sums = 131072 threads
    reduce_kernel<<<(BB * NN * 4) / 256, 256>>>(power, bias, out);
}